// round 14
// baseline (speedup 1.0000x reference)
#include <cuda_runtime.h>
#include <cstdint>

#define NTOT 150000
#define CCH  256
#define TM   128
#define TN   64
#define KC   32
#define ASTR 36    // A row stride: bank = 4*(lane>>2)+(lane&3) -> conflict-free
#define BSTR 68    // B row stride: 68%32=4 -> bank = 4*(lane&3)+(lane>>2) -> conflict-free

// ---- smem layout (float words) ----
#define WA_STG (160 * ASTR)              // 5760  (128 dense + 32 ext rows)
#define SB_OFF (2 * WA_STG)              // 11520
#define WB_STG (3 * KC * BSTR)           // 6528  (mid, tap-, tap+)
#define SCORR  (SB_OFF + 2 * WB_STG)     // 24576
#define CSTR   65
#define OFF_R2I (SCORR + 32 * CSTR)      // 26656  int[3][128]
#define OFF_LN  (OFF_R2I + 384)          // int[3][32]  (2 taps x 16)
#define OFF_LC  (OFF_LN + 96)            // int[3][32]
#define OFF_CNT (OFF_LC + 96)            // cntT[3][2] + cntM[3] = 9 ints
#define SMEM_WORDS (OFF_CNT + 12)
#define SMEM_BYTES (SMEM_WORDS * 4)      // 109,008 B -> 2 CTAs/SM

__device__ __forceinline__ void cpa16(uint32_t dst, const float* src) {
    asm volatile("cp.async.ca.shared.global [%0], [%1], 16;" :: "r"(dst), "l"(src));
}
__device__ __forceinline__ void cpa16z(uint32_t dst, const float* src, int sb) {
    asm volatile("cp.async.ca.shared.global [%0], [%1], 16, %2;" :: "r"(dst), "l"(src), "r"(sb));
}
__device__ __forceinline__ void mma_tf32(float c[4], const uint32_t a[4], const uint32_t b[2]) {
    asm volatile("mma.sync.aligned.m16n8k8.row.col.f32.tf32.tf32.f32 "
                 "{%0,%1,%2,%3}, {%4,%5,%6,%7}, {%8,%9}, {%0,%1,%2,%3};"
                 : "+f"(c[0]), "+f"(c[1]), "+f"(c[2]), "+f"(c[3])
                 : "r"(a[0]), "r"(a[1]), "r"(a[2]), "r"(a[3]),
                   "r"(b[0]), "r"(b[1]));
}

__global__ void __launch_bounds__(256, 2)
recon_block_kernel(const float* __restrict__ feats,
                   const float* __restrict__ w1, const float* __restrict__ w2,
                   const float* __restrict__ w3,
                   const float* __restrict__ g1, const float* __restrict__ b1,
                   const float* __restrict__ g2, const float* __restrict__ b2,
                   const float* __restrict__ g3, const float* __restrict__ b3,
                   const int* __restrict__ nx, const int* __restrict__ ny,
                   const int* __restrict__ nz,
                   float* __restrict__ out)
{
    extern __shared__ float sm[];
    float* CorrC = sm + SCORR;               // [32][65] compact correction rows
    int* r2i   = (int*)(sm + OFF_R2I);       // [3][128] dense row -> compact idx | -1 | -2
    int* listN = (int*)(sm + OFF_LN);        // [3][2*16] neighbor row or -1
    int* listC = (int*)(sm + OFF_LC);        // [3][2*16] compact idx or -1
    int* cnts  = (int*)(sm + OFF_CNT);       // cntT[3][2] then cntM[3]

    const int tid  = threadIdx.x;
    const int lane = tid & 31;
    const int wid  = tid >> 5;
    const int warpM = wid & 3;
    const int warpN = wid >> 2;
    const int extTap = wid & 1;              // correction tap owned by this warp
    const int extN0  = (wid >> 1) * 16;      // 16-col slab for corrections
    const int rowBase = blockIdx.y * TM;
    const int colBase = blockIdx.x * TN;

    uint32_t smb;
    asm("{ .reg .u64 t; cvta.to.shared.u64 t, %1; cvt.u32.u64 %0, t; }" : "=r"(smb) : "l"(sm));

    // loader decomposition (A dense + ext + B share tid mapping)
    const int la_r0 = tid >> 3;              // 0..31
    const int la_q  = tid & 7;

    // dense A source pointers (rows clamped for ragged tail)
    const float* srcD[4];
#pragma unroll
    for (int p = 0; p < 4; p++) {
        int gr = rowBase + la_r0 + 32 * p;
        if (gr >= NTOT) gr = NTOT - 1;
        srcD[p] = feats + (size_t)gr * CCH + la_q * 4;
    }

    // ---- prebuild correction lists for all 3 axes ----
    if (tid < 96)  { listN[tid] = -1; listC[tid] = -1; }
    if (tid < 9)   cnts[tid] = 0;
    if (tid < 128) { r2i[tid] = -1; r2i[128 + tid] = -1; r2i[256 + tid] = -1; }
    __syncthreads();
    if (tid < 128) {
        const int gr = rowBase + tid;
        if (gr < NTOT) {
            for (int ax = 0; ax < 3; ax++) {
                const int* nb_ = ax == 0 ? nx : ax == 1 ? ny : nz;
                const int nbm = nb_[gr * 3];
                const int nbp = nb_[gr * 3 + 2];
                if (nbm >= 0 || nbp >= 0) {
                    const int m = atomicAdd(&cnts[6 + ax], 1);
                    int ci = (m < 32) ? m : -2;
                    if (nbm >= 0) {
                        const int it = atomicAdd(&cnts[ax * 2 + 0], 1);
                        if (it < 16 && ci >= 0) { listN[ax * 32 + it] = nbm; listC[ax * 32 + it] = ci; }
                        else ci = -2;
                    }
                    if (nbp >= 0) {
                        const int it = atomicAdd(&cnts[ax * 2 + 1], 1);
                        if (it < 16 && ci >= 0) { listN[ax * 32 + 16 + it] = nbp; listC[ax * 32 + 16 + it] = ci; }
                        else ci = -2;
                    }
                    r2i[ax * 128 + tid] = ci;
                }
            }
        }
    }
    __syncthreads();

    const float bn_rs = rsqrtf(1.f + 1e-5f);
    float ssum[2][4][4];
#pragma unroll
    for (int mi = 0; mi < 2; mi++)
#pragma unroll
        for (int ni = 0; ni < 4; ni++)
#pragma unroll
            for (int k = 0; k < 4; k++) ssum[mi][ni][k] = 0.f;

// issue async loads for global chunk: dense A + ext A + 3 B tiles, one commit group
#define ISSUE(WSEL, LNB, K0, BUF) do {                                          \
    const int k0_ = (K0);                                                       \
    const uint32_t ab_ = smb + (BUF) * (WA_STG * 4);                            \
    const uint32_t bb_ = smb + (SB_OFF + (BUF) * WB_STG) * 4;                   \
    _Pragma("unroll")                                                           \
    for (int p_ = 0; p_ < 4; p_++)                                              \
        cpa16(ab_ + ((la_r0 + 32 * p_) * ASTR + la_q * 4) * 4, srcD[p_] + k0_); \
    {                                                                           \
        const int nb_ = (LNB)[la_r0];                                           \
        const float* es_ = feats + (size_t)(nb_ < 0 ? 0 : nb_) * CCH + la_q * 4 + k0_; \
        cpa16z(ab_ + ((128 + la_r0) * ASTR + la_q * 4) * 4, es_, nb_ >= 0 ? 16 : 0);   \
    }                                                                           \
    _Pragma("unroll")                                                           \
    for (int it_ = 0; it_ < 6; it_++) {                                         \
        const int tile_ = it_ >> 1;                                             \
        const int idx_  = (tid + it_ * 256) & 511;                              \
        const int r_ = idx_ >> 4, q_ = idx_ & 15;                               \
        const int tap_ = tile_ == 0 ? 1 : tile_ == 1 ? 0 : 2;                   \
        cpa16(bb_ + (tile_ * (KC * BSTR) + r_ * BSTR + q_ * 4) * 4,             \
              (WSEL) + (size_t)tap_ * 65536 + (size_t)(k0_ + r_) * CCH + colBase + q_ * 4); \
    }                                                                           \
    asm volatile("cp.async.commit_group;" ::: "memory");                        \
} while (0)

    // prologue: chunks 0 and 1 of axis 0
    ISSUE(w1, listN, 0, 0);
    ISSUE(w1, listN, KC, 1);

#pragma unroll 1
    for (int axis = 0; axis < 3; axis++) {
        const float* w   = axis == 0 ? w1 : axis == 1 ? w2 : w3;
        const float* gam = axis == 0 ? g1 : axis == 1 ? g2 : g3;
        const float* bet = axis == 0 ? b1 : axis == 1 ? b2 : b3;
        const int*   nbr = axis == 0 ? nx : axis == 1 ? ny : nz;

        __syncthreads();                         // prev epilogue done with CorrC
        for (int i = tid; i < 32 * CSTR; i += 256) CorrC[i] = 0.f;

        float acc[2][4][4];
        float aex[2][4];
#pragma unroll
        for (int mi = 0; mi < 2; mi++)
#pragma unroll
            for (int ni = 0; ni < 4; ni++)
#pragma unroll
                for (int k = 0; k < 4; k++) acc[mi][ni][k] = 0.f;
#pragma unroll
        for (int e = 0; e < 2; e++)
#pragma unroll
            for (int k = 0; k < 4; k++) aex[e][k] = 0.f;

#pragma unroll 1
        for (int ch = 0; ch < 8; ch++) {
            const int L = axis * 8 + ch;
            if (L < 23) asm volatile("cp.async.wait_group 1;" ::: "memory");
            else        asm volatile("cp.async.wait_group 0;" ::: "memory");
            __syncthreads();

            const float* Ab = sm + (ch & 1) * WA_STG;
            const float* Bm = sm + SB_OFF + (ch & 1) * WB_STG;
            const float* Bt = Bm + (1 + extTap) * (KC * BSTR);

#pragma unroll
            for (int kst = 0; kst < 4; kst++) {
                const int kq = kst * 8 + (lane & 3);
                uint32_t a[2][4], b[4][2];
#pragma unroll
                for (int mi = 0; mi < 2; mi++) {
                    const int r0 = warpM * 32 + mi * 16 + (lane >> 2);
                    a[mi][0] = __float_as_uint(Ab[r0 * ASTR + kq]);
                    a[mi][1] = __float_as_uint(Ab[(r0 + 8) * ASTR + kq]);
                    a[mi][2] = __float_as_uint(Ab[r0 * ASTR + kq + 4]);
                    a[mi][3] = __float_as_uint(Ab[(r0 + 8) * ASTR + kq + 4]);
                }
#pragma unroll
                for (int ni = 0; ni < 4; ni++) {
                    const int n0 = warpN * 32 + ni * 8 + (lane >> 2);
                    b[ni][0] = __float_as_uint(Bm[kq * BSTR + n0]);
                    b[ni][1] = __float_as_uint(Bm[(kq + 4) * BSTR + n0]);
                }
#pragma unroll
                for (int mi = 0; mi < 2; mi++)
#pragma unroll
                    for (int ni = 0; ni < 4; ni++)
                        mma_tf32(acc[mi][ni], a[mi], b[ni]);

                // correction rows: m16 tile per tap, 16-col slab per warp
                {
                    const int er0 = 128 + 16 * extTap + (lane >> 2);
                    uint32_t ea[4], eb[2][2];
                    ea[0] = __float_as_uint(Ab[er0 * ASTR + kq]);
                    ea[1] = __float_as_uint(Ab[(er0 + 8) * ASTR + kq]);
                    ea[2] = __float_as_uint(Ab[er0 * ASTR + kq + 4]);
                    ea[3] = __float_as_uint(Ab[(er0 + 8) * ASTR + kq + 4]);
#pragma unroll
                    for (int e = 0; e < 2; e++) {
                        const int n0e = extN0 + e * 8 + (lane >> 2);
                        eb[e][0] = __float_as_uint(Bt[kq * BSTR + n0e]);
                        eb[e][1] = __float_as_uint(Bt[(kq + 4) * BSTR + n0e]);
                    }
                    mma_tf32(aex[0], ea, eb[0]);
                    mma_tf32(aex[1], ea, eb[1]);
                }
            }
            __syncthreads();

            // prefetch global chunk L+2 (crosses axis boundary seamlessly)
            const int Ln = L + 2;
            if (Ln <= 23) {
                const int nA = Ln >> 3, nC = Ln & 7;
                const float* wsel = nA == 0 ? w1 : nA == 1 ? w2 : w3;
                const int* lnb = listN + nA * 32;
                ISSUE(wsel, lnb, nC * KC, Ln & 1);
            }
        }

        // ---- scatter correction accumulators into compact CorrC ----
#pragma unroll
        for (int h = 0; h < 2; h++) {
            const int idx = (lane >> 2) + 8 * h;
            const int ci = listC[axis * 32 + extTap * 16 + idx];
            if (ci >= 0) {
#pragma unroll
                for (int e = 0; e < 2; e++)
#pragma unroll
                    for (int j = 0; j < 2; j++)
                        atomicAdd(&CorrC[ci * CSTR + extN0 + e * 8 + 2 * (lane & 3) + j],
                                  aex[e][2 * h + j]);
            }
        }
        __syncthreads();

        // ---- epilogue: ssum += sigmoid((dense + corr) * scale + beta) ----
#pragma unroll
        for (int mi = 0; mi < 2; mi++) {
#pragma unroll
            for (int h = 0; h < 2; h++) {
                const int rl = warpM * 32 + mi * 16 + (lane >> 2) + 8 * h;
                const int ci = r2i[axis * 128 + rl];
                const int gr = rowBase + rl;
#pragma unroll
                for (int ni = 0; ni < 4; ni++) {
#pragma unroll
                    for (int j = 0; j < 2; j++) {
                        const int cl = warpN * 32 + ni * 8 + 2 * (lane & 3) + j;
                        float y = acc[mi][ni][2 * h + j];
                        if (ci >= 0) y += CorrC[ci * CSTR + cl];
                        else if (ci == -2) {
                            // overflow fallback: recompute both taps (never runs in practice)
                            float corr = 0.f;
                            const int nbm = nbr[gr * 3], nbp = nbr[gr * 3 + 2];
                            if (nbm >= 0) {
                                const float* f = feats + (size_t)nbm * CCH;
                                const float* wp = w + colBase + cl;
                                for (int k = 0; k < CCH; k++) corr += f[k] * wp[(size_t)k * CCH];
                            }
                            if (nbp >= 0) {
                                const float* f = feats + (size_t)nbp * CCH;
                                const float* wp = w + (size_t)2 * 65536 + colBase + cl;
                                for (int k = 0; k < CCH; k++) corr += f[k] * wp[(size_t)k * CCH];
                            }
                            y += corr;
                        }
                        const float sc = gam[colBase + cl] * bn_rs;
                        const float bb = bet[colBase + cl];
                        y = y * sc + bb;
                        ssum[mi][ni][2 * h + j] += 1.f / (1.f + __expf(-y));
                    }
                }
            }
        }
    }
#undef ISSUE

    // ---- final: out = ssum * feats ----
#pragma unroll
    for (int mi = 0; mi < 2; mi++) {
#pragma unroll
        for (int h = 0; h < 2; h++) {
            const int gr = rowBase + warpM * 32 + mi * 16 + (lane >> 2) + 8 * h;
            if (gr >= NTOT) continue;
#pragma unroll
            for (int ni = 0; ni < 4; ni++) {
                const int c0 = colBase + warpN * 32 + ni * 8 + 2 * (lane & 3);
                const float2 f = *reinterpret_cast<const float2*>(feats + (size_t)gr * CCH + c0);
                float2 o;
                o.x = ssum[mi][ni][2 * h + 0] * f.x;
                o.y = ssum[mi][ni][2 * h + 1] * f.y;
                *reinterpret_cast<float2*>(out + (size_t)gr * CCH + c0) = o;
            }
        }
    }
}

extern "C" void kernel_launch(void* const* d_in, const int* in_sizes, int n_in,
                              void* d_out, int out_size) {
    (void)in_sizes; (void)n_in; (void)out_size;
    const float* feats = (const float*)d_in[0];
    const float* w1    = (const float*)d_in[1];
    const float* w2    = (const float*)d_in[2];
    const float* w3    = (const float*)d_in[3];
    const float* g1    = (const float*)d_in[4];
    const float* b1    = (const float*)d_in[5];
    const float* g2    = (const float*)d_in[6];
    const float* b2    = (const float*)d_in[7];
    const float* g3    = (const float*)d_in[8];
    const float* b3    = (const float*)d_in[9];
    const int*   nx    = (const int*)d_in[10];
    const int*   ny    = (const int*)d_in[11];
    const int*   nz    = (const int*)d_in[12];
    float* out = (float*)d_out;

    cudaFuncSetAttribute(recon_block_kernel,
                         cudaFuncAttributeMaxDynamicSharedMemorySize, SMEM_BYTES);

    dim3 grid(CCH / TN, (NTOT + TM - 1) / TM);   // (4, 1172)
    recon_block_kernel<<<grid, 256, SMEM_BYTES>>>(feats, w1, w2, w3,
                                                  g1, b1, g2, b2, g3, b3,
                                                  nx, ny, nz, out);
}

// round 16
// speedup vs baseline: 1.4070x; 1.4070x over previous
#include <cuda_runtime.h>
#include <cuda_fp16.h>
#include <cstdint>

#define NTOT 150000
#define CCH  256
#define TM   128
#define TN   64
#define KC   32      // k elements per chunk (2 ksteps of k16)
#define ASTR 20      // A row stride in half2 words: (r*20+q) conflict-free
#define BSTR 20      // B row stride in half2 words

// ---- smem layout (32-bit words) ----
#define WA (160 * ASTR)              // 3200 per buf (128 dense + 32 ext rows)
#define WB (3 * 64 * BSTR)           // 3840 per buf (mid, tap-, tap+)
#define SBOFF (2 * WA)               // 6400
#define SCORR (SBOFF + 2 * WB)       // 14080
#define CSTR 65
#define OFF_R2I (SCORR + 32 * CSTR)  // 16160
#define OFF_LN  (OFF_R2I + 384)
#define OFF_LC  (OFF_LN + 96)
#define OFF_CNT (OFF_LC + 96)
#define SMEM_WORDS (OFF_CNT + 12)
#define SMEM_BYTES (SMEM_WORDS * 4)  // 66,992 B -> 2 CTAs/SM

__device__ __half g_fh[(size_t)NTOT * CCH];   // feats as fp16
__device__ __half g_wTh[9 * 256 * 256];       // [axis*3+tap][n][k] fp16 (transposed)

// ---------------- conversion pre-kernels ----------------
__global__ void conv_feats(const float* __restrict__ f) {
    const size_t i = ((size_t)blockIdx.x * blockDim.x + threadIdx.x) * 4;
    if (i < (size_t)NTOT * CCH) {
        const float4 v = *reinterpret_cast<const float4*>(f + i);
        *reinterpret_cast<__half2*>(g_fh + i)     = __floats2half2_rn(v.x, v.y);
        *reinterpret_cast<__half2*>(g_fh + i + 2) = __floats2half2_rn(v.z, v.w);
    }
}

__global__ void conv_w(const float* __restrict__ w1, const float* __restrict__ w2,
                       const float* __restrict__ w3) {
    __shared__ float t[32][33];
    const int at = blockIdx.x;                       // 0..8
    const float* w = at < 3 ? w1 : at < 6 ? w2 : w3;
    const float* src = w + (size_t)(at % 3) * 65536; // [k][n]
    const int n0 = blockIdx.y * 32, k0 = blockIdx.z * 32;
    t[threadIdx.y][threadIdx.x] = src[(size_t)(k0 + threadIdx.y) * 256 + n0 + threadIdx.x];
    __syncthreads();
    g_wTh[(size_t)at * 65536 + (size_t)(n0 + threadIdx.y) * 256 + k0 + threadIdx.x] =
        __float2half_rn(t[threadIdx.x][threadIdx.y]);
}

// ---------------- helpers ----------------
__device__ __forceinline__ void cpa16(uint32_t dst, const void* src) {
    asm volatile("cp.async.ca.shared.global [%0], [%1], 16;" :: "r"(dst), "l"(src));
}
__device__ __forceinline__ void cpa16z(uint32_t dst, const void* src, int sb) {
    asm volatile("cp.async.ca.shared.global [%0], [%1], 16, %2;" :: "r"(dst), "l"(src), "r"(sb));
}
__device__ __forceinline__ void mma_f16(float c[4], const uint32_t a[4], const uint32_t b[2]) {
    asm volatile("mma.sync.aligned.m16n8k16.row.col.f32.f16.f16.f32 "
                 "{%0,%1,%2,%3}, {%4,%5,%6,%7}, {%8,%9}, {%0,%1,%2,%3};"
                 : "+f"(c[0]), "+f"(c[1]), "+f"(c[2]), "+f"(c[3])
                 : "r"(a[0]), "r"(a[1]), "r"(a[2]), "r"(a[3]),
                   "r"(b[0]), "r"(b[1]));
}

__global__ void __launch_bounds__(256, 2)
recon_block_kernel(const float* __restrict__ feats,
                   const float* __restrict__ w1, const float* __restrict__ w2,
                   const float* __restrict__ w3,
                   const float* __restrict__ g1, const float* __restrict__ b1,
                   const float* __restrict__ g2, const float* __restrict__ b2,
                   const float* __restrict__ g3, const float* __restrict__ b3,
                   const int* __restrict__ nx, const int* __restrict__ ny,
                   const int* __restrict__ nz,
                   float* __restrict__ out)
{
    extern __shared__ float sm[];
    float* CorrC = sm + SCORR;               // [32][65] compact correction rows
    int* r2i   = (int*)(sm + OFF_R2I);       // [3][128] dense row -> compact idx | -1 | -2
    int* listN = (int*)(sm + OFF_LN);        // [3][32]  (16 tap- + 16 tap+) neighbor or -1
    int* listC = (int*)(sm + OFF_LC);        // [3][32]  compact idx or -1
    int* cnts  = (int*)(sm + OFF_CNT);       // cntT[3][2] then cntM[3]

    const int tid  = threadIdx.x;
    const int lane = tid & 31;
    const int wid  = tid >> 5;
    const int warpM = wid & 3;
    const int warpN = wid >> 2;
    const int extTap = wid & 1;
    const int extN0  = (wid >> 1) * 16;
    const int rowBase = blockIdx.y * TM;
    const int colBase = blockIdx.x * TN;

    uint32_t smb;
    asm("{ .reg .u64 t; cvta.to.shared.u64 t, %1; cvt.u32.u64 %0, t; }" : "=r"(smb) : "l"(sm));

    // loader: row/n = tid>>2 (0..63), quad = tid&3 (16B = 8 halves)
    const int la_r = tid >> 2;
    const int la_q = tid & 3;

    int gr0 = rowBase + la_r;      if (gr0 >= NTOT) gr0 = NTOT - 1;
    int gr1 = rowBase + la_r + 64; if (gr1 >= NTOT) gr1 = NTOT - 1;
    const __half* srcD0 = g_fh + (size_t)gr0 * CCH + la_q * 8;
    const __half* srcD1 = g_fh + (size_t)gr1 * CCH + la_q * 8;

    // ---- prebuild correction lists for all 3 axes ----
    if (tid < 96)  { listN[tid] = -1; listC[tid] = -1; }
    if (tid < 9)   cnts[tid] = 0;
    if (tid < 128) { r2i[tid] = -1; r2i[128 + tid] = -1; r2i[256 + tid] = -1; }
    __syncthreads();
    if (tid < 128) {
        const int gr = rowBase + tid;
        if (gr < NTOT) {
            for (int ax = 0; ax < 3; ax++) {
                const int* nb_ = ax == 0 ? nx : ax == 1 ? ny : nz;
                const int nbm = nb_[gr * 3];
                const int nbp = nb_[gr * 3 + 2];
                if (nbm >= 0 || nbp >= 0) {
                    const int m = atomicAdd(&cnts[6 + ax], 1);
                    int ci = (m < 32) ? m : -2;
                    if (nbm >= 0) {
                        const int it = atomicAdd(&cnts[ax * 2 + 0], 1);
                        if (it < 16 && ci >= 0) { listN[ax * 32 + it] = nbm; listC[ax * 32 + it] = ci; }
                        else ci = -2;
                    }
                    if (nbp >= 0) {
                        const int it = atomicAdd(&cnts[ax * 2 + 1], 1);
                        if (it < 16 && ci >= 0) { listN[ax * 32 + 16 + it] = nbp; listC[ax * 32 + 16 + it] = ci; }
                        else ci = -2;
                    }
                    r2i[ax * 128 + tid] = ci;
                }
            }
        }
    }
    __syncthreads();

    const float bn_rs = rsqrtf(1.f + 1e-5f);
    float ssum[2][4][4];
#pragma unroll
    for (int mi = 0; mi < 2; mi++)
#pragma unroll
        for (int ni = 0; ni < 4; ni++)
#pragma unroll
            for (int k = 0; k < 4; k++) ssum[mi][ni][k] = 0.f;

// one global chunk: dense A (2 rows/thread) + ext A + 3 B tiles, one commit group
#define ISSUE(AX, LNB, K0, BUF) do {                                            \
    const int k0_ = (K0);                                                       \
    const uint32_t ab_ = smb + ((BUF) * WA) * 4;                                \
    const uint32_t bb_ = smb + (SBOFF + (BUF) * WB) * 4;                        \
    cpa16(ab_ + (la_r * ASTR + la_q * 4) * 4, srcD0 + k0_);                     \
    cpa16(ab_ + ((la_r + 64) * ASTR + la_q * 4) * 4, srcD1 + k0_);              \
    if (tid < 128) {                                                            \
        const int nb_ = (LNB)[la_r];                                            \
        cpa16z(ab_ + ((128 + la_r) * ASTR + la_q * 4) * 4,                      \
               g_fh + (size_t)(nb_ < 0 ? 0 : nb_) * CCH + k0_ + la_q * 8,       \
               nb_ >= 0 ? 16 : 0);                                              \
    }                                                                           \
    _Pragma("unroll")                                                           \
    for (int tile_ = 0; tile_ < 3; tile_++) {                                   \
        const int tap_ = tile_ == 0 ? 1 : tile_ == 1 ? 0 : 2;                   \
        cpa16(bb_ + (tile_ * (64 * BSTR) + la_r * BSTR + la_q * 4) * 4,         \
              g_wTh + (size_t)((AX) * 3 + tap_) * 65536                         \
                    + (size_t)(colBase + la_r) * 256 + k0_ + la_q * 8);         \
    }                                                                           \
    asm volatile("cp.async.commit_group;" ::: "memory");                        \
} while (0)

    ISSUE(0, listN, 0, 0);
    ISSUE(0, listN, KC, 1);

#pragma unroll 1
    for (int axis = 0; axis < 3; axis++) {
        const float* w   = axis == 0 ? w1 : axis == 1 ? w2 : w3;
        const float* gam = axis == 0 ? g1 : axis == 1 ? g2 : g3;
        const float* bet = axis == 0 ? b1 : axis == 1 ? b2 : b3;
        const int*   nbr = axis == 0 ? nx : axis == 1 ? ny : nz;

        __syncthreads();
        for (int i = tid; i < 32 * CSTR; i += 256) CorrC[i] = 0.f;

        float acc[2][4][4];
        float aex[2][4];
#pragma unroll
        for (int mi = 0; mi < 2; mi++)
#pragma unroll
            for (int ni = 0; ni < 4; ni++)
#pragma unroll
                for (int k = 0; k < 4; k++) acc[mi][ni][k] = 0.f;
#pragma unroll
        for (int e = 0; e < 2; e++)
#pragma unroll
            for (int k = 0; k < 4; k++) aex[e][k] = 0.f;

#pragma unroll 1
        for (int ch = 0; ch < 8; ch++) {
            const int L = axis * 8 + ch;
            if (L < 23) asm volatile("cp.async.wait_group 1;" ::: "memory");
            else        asm volatile("cp.async.wait_group 0;" ::: "memory");
            __syncthreads();

            const uint32_t* Aw = (const uint32_t*)sm + (ch & 1) * WA;
            const uint32_t* Bm = (const uint32_t*)sm + SBOFF + (ch & 1) * WB;
            const uint32_t* Bt = Bm + (1 + extTap) * (64 * BSTR);

#pragma unroll
            for (int s = 0; s < 2; s++) {
                const int kw = s * 8 + (lane & 3);
                uint32_t a[2][4], b[4][2];
#pragma unroll
                for (int mi = 0; mi < 2; mi++) {
                    const int r0 = warpM * 32 + mi * 16 + (lane >> 2);
                    a[mi][0] = Aw[r0 * ASTR + kw];
                    a[mi][1] = Aw[(r0 + 8) * ASTR + kw];
                    a[mi][2] = Aw[r0 * ASTR + kw + 4];
                    a[mi][3] = Aw[(r0 + 8) * ASTR + kw + 4];
                }
#pragma unroll
                for (int ni = 0; ni < 4; ni++) {
                    const int n0 = warpN * 32 + ni * 8 + (lane >> 2);
                    b[ni][0] = Bm[n0 * BSTR + kw];
                    b[ni][1] = Bm[n0 * BSTR + kw + 4];
                }
#pragma unroll
                for (int mi = 0; mi < 2; mi++)
#pragma unroll
                    for (int ni = 0; ni < 4; ni++)
                        mma_f16(acc[mi][ni], a[mi], b[ni]);

                // correction rows: m16 tile per tap, 16-col slab per warp
                {
                    const int er0 = 128 + 16 * extTap + (lane >> 2);
                    uint32_t ea[4], eb[2][2];
                    ea[0] = Aw[er0 * ASTR + kw];
                    ea[1] = Aw[(er0 + 8) * ASTR + kw];
                    ea[2] = Aw[er0 * ASTR + kw + 4];
                    ea[3] = Aw[(er0 + 8) * ASTR + kw + 4];
#pragma unroll
                    for (int e = 0; e < 2; e++) {
                        const int n0e = extN0 + e * 8 + (lane >> 2);
                        eb[e][0] = Bt[n0e * BSTR + kw];
                        eb[e][1] = Bt[n0e * BSTR + kw + 4];
                    }
                    mma_f16(aex[0], ea, eb[0]);
                    mma_f16(aex[1], ea, eb[1]);
                }
            }
            __syncthreads();

            const int Ln = L + 2;
            if (Ln <= 23) {
                const int nA = Ln >> 3, nC = Ln & 7;
                const int* lnb = listN + nA * 32;
                ISSUE(nA, lnb, nC * KC, Ln & 1);
            }
        }

        // ---- scatter correction accumulators into compact CorrC ----
#pragma unroll
        for (int h = 0; h < 2; h++) {
            const int idx = (lane >> 2) + 8 * h;
            const int ci = listC[axis * 32 + extTap * 16 + idx];
            if (ci >= 0) {
#pragma unroll
                for (int e = 0; e < 2; e++)
#pragma unroll
                    for (int j = 0; j < 2; j++)
                        atomicAdd(&CorrC[ci * CSTR + extN0 + e * 8 + 2 * (lane & 3) + j],
                                  aex[e][2 * h + j]);
            }
        }
        __syncthreads();

        // ---- epilogue: ssum += sigmoid((dense + corr) * scale + beta) ----
#pragma unroll
        for (int mi = 0; mi < 2; mi++) {
#pragma unroll
            for (int h = 0; h < 2; h++) {
                const int rl = warpM * 32 + mi * 16 + (lane >> 2) + 8 * h;
                const int ci = r2i[axis * 128 + rl];
                const int gr = rowBase + rl;
#pragma unroll
                for (int ni = 0; ni < 4; ni++) {
#pragma unroll
                    for (int j = 0; j < 2; j++) {
                        const int cl = warpN * 32 + ni * 8 + 2 * (lane & 3) + j;
                        float y = acc[mi][ni][2 * h + j];
                        if (ci >= 0) y += CorrC[ci * CSTR + cl];
                        else if (ci == -2) {
                            // overflow fallback (f32 exact; practically never runs)
                            float corr = 0.f;
                            const int nbm = nbr[gr * 3], nbp = nbr[gr * 3 + 2];
                            if (nbm >= 0) {
                                const float* f = feats + (size_t)nbm * CCH;
                                const float* wp = w + colBase + cl;
                                for (int k = 0; k < CCH; k++) corr += f[k] * wp[(size_t)k * CCH];
                            }
                            if (nbp >= 0) {
                                const float* f = feats + (size_t)nbp * CCH;
                                const float* wp = w + (size_t)2 * 65536 + colBase + cl;
                                for (int k = 0; k < CCH; k++) corr += f[k] * wp[(size_t)k * CCH];
                            }
                            y += corr;
                        }
                        y = y * (gam[colBase + cl] * bn_rs) + bet[colBase + cl];
                        ssum[mi][ni][2 * h + j] += 1.f / (1.f + __expf(-y));
                    }
                }
            }
        }
    }
#undef ISSUE

    // ---- final: out = ssum * feats (f32, exact) ----
#pragma unroll
    for (int mi = 0; mi < 2; mi++) {
#pragma unroll
        for (int h = 0; h < 2; h++) {
            const int gr = rowBase + warpM * 32 + mi * 16 + (lane >> 2) + 8 * h;
            if (gr >= NTOT) continue;
#pragma unroll
            for (int ni = 0; ni < 4; ni++) {
                const int c0 = colBase + warpN * 32 + ni * 8 + 2 * (lane & 3);
                const float2 f = *reinterpret_cast<const float2*>(feats + (size_t)gr * CCH + c0);
                float2 o;
                o.x = ssum[mi][ni][2 * h + 0] * f.x;
                o.y = ssum[mi][ni][2 * h + 1] * f.y;
                *reinterpret_cast<float2*>(out + (size_t)gr * CCH + c0) = o;
            }
        }
    }
}

extern "C" void kernel_launch(void* const* d_in, const int* in_sizes, int n_in,
                              void* d_out, int out_size) {
    (void)in_sizes; (void)n_in; (void)out_size;
    const float* feats = (const float*)d_in[0];
    const float* w1    = (const float*)d_in[1];
    const float* w2    = (const float*)d_in[2];
    const float* w3    = (const float*)d_in[3];
    const float* g1    = (const float*)d_in[4];
    const float* b1    = (const float*)d_in[5];
    const float* g2    = (const float*)d_in[6];
    const float* b2    = (const float*)d_in[7];
    const float* g3    = (const float*)d_in[8];
    const float* b3    = (const float*)d_in[9];
    const int*   nx    = (const int*)d_in[10];
    const int*   ny    = (const int*)d_in[11];
    const int*   nz    = (const int*)d_in[12];
    float* out = (float*)d_out;

    cudaFuncSetAttribute(recon_block_kernel,
                         cudaFuncAttributeMaxDynamicSharedMemorySize, SMEM_BYTES);

    conv_feats<<<(NTOT * CCH / 4 + 255) / 256, 256>>>(feats);
    conv_w<<<dim3(9, 8, 8), dim3(32, 32)>>>(w1, w2, w3);

    dim3 grid(CCH / TN, (NTOT + TM - 1) / TM);   // (4, 1172)
    recon_block_kernel<<<grid, 256, SMEM_BYTES>>>(feats, w1, w2, w3,
                                                  g1, b1, g2, b2, g3, b3,
                                                  nx, ny, nz, out);
}